// round 13
// baseline (speedup 1.0000x reference)
#include <cuda_runtime.h>
#include <cstdint>

// Problem dims (fixed)
#define ZD 16
#define YD 384
#define XD 384
#define NWIN_I 17     // z-pairs
#define NW 385        // window rows
#define NPX 384       // columns per row
#define NGX 48        // 8-window groups; group 47 also does edge window x=384
#define TOTAL_B_THREADS (NWIN_I * NW * NGX)              // 314160
#define K2_BLK 256
#define B_BLOCKS ((TOTAL_B_THREADS + K2_BLK - 1) / K2_BLK)   // 1228
#define NP_WIN 148225.0                                   // 385*385
#define SLAB (YD * XD)                                    // 147456

// Scratch (static __device__ — zero-initialized, no allocation)
// Fully y+z combined per-column window-row records:
__device__ float         g_F[NWIN_I * NW * NPX];   // 4-corner (s-l)^2 column sums
__device__ unsigned char g_W[NWIN_I * NW * NPX];   // column code: lab nibble @0-3, pred @4-7 (bit m=dz*2+dy)
__device__ float2        g_SW[NWIN_I * NW * NPX];  // 4-corner (softplus(p), softplus(-p)) sums
__device__ float         g_part[3 * B_BLOCKS];
__device__ unsigned      g_count;

// ---------------------------------------------------------------------------
// k1: one thread per (window-row w, x). Owns original rows y0=w-1 (dy=0) and
// y1=w (dy=1); walks z emitting 17 fully-combined column records.
// h0/h1 are uniform per block (w = blockIdx.x) -> no divergence.
__global__ void k1(const float* __restrict__ pred, const int* __restrict__ lab) {
    int x = threadIdx.x;       // 0..383
    int w = blockIdx.x;        // 0..384
    if (x == 0 && w == 0) g_count = 0u;
    bool h0 = (w > 0);         // y0 = w-1 valid
    bool h1 = (w < NPX);       // y1 = w valid
    int b0 = (w - 1) * XD + x;
    int b1 = w * XD + x;

    float dP = 0.f, spP = 0.f, snP = 0.f;
    unsigned cP = 0u;
    int o = w * NPX + x;
#pragma unroll 4
    for (int z = 0; z < ZD; z++) {
        float d = 0.f, sp = 0.f, sn = 0.f;
        unsigned cc = 0u;
        if (h0) {
            float p = __ldg(&pred[z * SLAB + b0]);
            int   l = __ldg(&lab[z * SLAB + b0]);
            float s = __fdividef(1.f, 1.f + __expf(-p));
            float f = (float)l;
            d = (s - f) * (s - f);
            float s_p = fmaxf(p, 0.f) + __logf(1.f + __expf(-fabsf(p)));
            sp = s_p; sn = s_p - p;
            cc = (unsigned)(l & 1) | (p > 0.f ? 0x10u : 0u);       // dy=0 -> bits 0,4
        }
        if (h1) {
            float p = __ldg(&pred[z * SLAB + b1]);
            int   l = __ldg(&lab[z * SLAB + b1]);
            float s = __fdividef(1.f, 1.f + __expf(-p));
            float f = (float)l;
            d += (s - f) * (s - f);
            float s_p = fmaxf(p, 0.f) + __logf(1.f + __expf(-fabsf(p)));
            sp += s_p; sn += s_p - p;
            cc |= ((unsigned)(l & 1) | (p > 0.f ? 0x10u : 0u)) << 1;  // dy=1 -> bits 1,5
        }
        int oo = z * (NW * NPX) + o;     // record i=z: dz=0 <- z-1 data (prev), dz=1 <- z
        g_F[oo]  = dP + d;
        g_W[oo]  = (unsigned char)(cP | (cc << 2));   // prev z at m=0,1 ; cur z at m=2,3
        g_SW[oo] = make_float2(spP + sp, snP + sn);
        dP = d; spP = sp; snP = sn; cP = cc;
    }
    int oo = ZD * (NW * NPX) + o;        // record i=16: only dz=0 (z=15)
    g_F[oo]  = dP;
    g_W[oo]  = (unsigned char)cP;
    g_SW[oo] = make_float2(spP, snP);
}

// ---------------------------------------------------------------------------
__device__ __forceinline__ float warp_sum(float v) {
#pragma unroll
    for (int off = 16; off > 0; off >>= 1)
        v += __shfl_down_sync(0xffffffffu, v, off);
    return v;
}

// ---------------------------------------------------------------------------
// k2: each thread sweeps 8 consecutive windows along x for fixed (i, w).
// Window x combines columns x-1 (left, dx=0) and x (right, dx=1):
//   q = F[x-1] + F[x];  lidx = (leftLab<<4)|rightLab;  pidx likewise.
// Global loads are issued BEFORE the LUT-build sync to overlap latency.
__global__ void __launch_bounds__(K2_BLK, 8)
k2(const float* __restrict__ area, float* __restrict__ out) {
    __shared__ float a_sh[256];
    __shared__ float wN[8], wD[8], wB[8];
    __shared__ bool is_last;
    int tid = threadIdx.x;

    int t = blockIdx.x * K2_BLK + tid;
    bool valid = (t < TOTAL_B_THREADS);
    int g = 0, w = 0, i = 0, x0 = 0, rF = 0;
    float4 f0 = make_float4(0.f, 0.f, 0.f, 0.f), f1 = f0;
    uint2 wv = make_uint2(0u, 0u);
    float Fp = 0.f;
    unsigned cbp = 0u;
    if (valid) {
        g = t % NGX;
        int rem = t / NGX;
        w = rem % NW;
        i = rem / NW;
        x0 = g * 8;
        rF = (i * NW + w) * NPX;
        f0 = *reinterpret_cast<const float4*>(g_F + rF + x0);
        f1 = *reinterpret_cast<const float4*>(g_F + rF + x0 + 4);
        wv = *reinterpret_cast<const uint2*>(g_W + rF + x0);
        if (x0 > 0) {
            Fp  = g_F[rF + x0 - 1];
            cbp = g_W[rF + x0 - 1];
        }
    }

    // permuted area LUT: index = (leftcol_nibble<<4)|rightcol_nibble,
    // nibble bit m = dz*2+dy -> true byte bit 2m+dx (left dx=0, right dx=1)
    {
        int a = tid >> 4, b = tid & 15;
        int byte = 0;
#pragma unroll
        for (int m = 0; m < 4; m++) {
            byte |= ((a >> m) & 1) << (2 * m);
            byte |= ((b >> m) & 1) << (2 * m + 1);
        }
        a_sh[tid] = __ldg(&area[byte]);
    }
    __syncthreads();

    float S1 = 0.f, S2 = 0.f, Sq = 0.f, accB = 0.f;
    if (valid) {
#pragma unroll
        for (int j = 0; j < 2; j++) {
            float4 f = j ? f1 : f0;
            unsigned cw = j ? wv.y : wv.x;
            // prevw byte k = code of column k-1 (byte0 = carry)
            unsigned prevw = __byte_perm(cw, cbp, 0x2104);
            // L byte k = lidx of window k ; P byte k = pidx of window k
            unsigned L = ((prevw << 4) & 0xF0F0F0F0u) | (cw & 0x0F0F0F0Fu);
            unsigned P = (prevw & 0xF0F0F0F0u) | ((cw >> 4) & 0x0F0F0F0Fu);

            float q0 = Fp + f.x;
            float q1 = f.x + f.y;
            float q2 = f.y + f.z;
            float q3 = f.z + f.w;

            float la0 = a_sh[L & 0xFFu];
            float la1 = a_sh[(L >> 8) & 0xFFu];
            float la2 = a_sh[(L >> 16) & 0xFFu];
            float la3 = a_sh[L >> 24];
            float pa0 = a_sh[P & 0xFFu];
            float pa1 = a_sh[(P >> 8) & 0xFFu];
            float pa2 = a_sh[(P >> 16) & 0xFFu];
            float pa3 = a_sh[P >> 24];

            Sq = fmaf(q0, la0, Sq);
            Sq = fmaf(q1, la1, Sq);
            Sq = fmaf(q2, la2, Sq);
            Sq = fmaf(q3, la3, Sq);
            S1 += (la0 + la1) + (la2 + la3);
            S2 += (pa0 + pa1) + (pa2 + pa3);

            // rare path: window label byte 0 -> sum softplus(p); 255 -> softplus(-p)
            unsigned r = __vcmpeq4(L, 0u) | __vcmpeq4(L, 0xFFFFFFFFu);
            if (r) {
#pragma unroll
                for (int k = 0; k < 4; k++) {
                    unsigned lb = (L >> (8 * k)) & 0xFFu;
                    if (lb == 0u || lb == 255u) {
                        int x = x0 + 4 * j + k;     // window; cols x-1, x
                        float2 sR = g_SW[rF + x];
                        float s0 = sR.x, s1 = sR.y;
                        if (x > 0) {
                            float2 sL = g_SW[rF + x - 1];
                            s0 += sL.x; s1 += sL.y;
                        }
                        accB += (lb == 255u) ? s1 : s0;
                    }
                }
            }

            Fp = f.w;
            cbp = cw >> 24;
        }

        // group 47: edge window x=384 (right column is zero padding)
        if (g == NGX - 1) {
            float q = Fp;
            unsigned lidx = (cbp << 4) & 0xF0u;
            unsigned pidx = cbp & 0xF0u;
            float la = a_sh[lidx];
            float pa = a_sh[pidx];
            Sq = fmaf(q, la, Sq);
            S1 += la;
            S2 += pa;
            if (lidx == 0u) {   // lidx==255 impossible (low nibble zero)
                float2 sL = g_SW[rF + 383];
                accB += sL.x;
            }
        }
    }
    float accN = fmaf(Sq, -0.125f, S1);   // sum of (1 - q/8)*la
    float accD = S1 + S2;

    // deterministic warp-shuffle reduction
    accN = warp_sum(accN);
    accD = warp_sum(accD);
    accB = warp_sum(accB);
    int lane = tid & 31, warp = tid >> 5;
    if (lane == 0) { wN[warp] = accN; wD[warp] = accD; wB[warp] = accB; }
    __syncthreads();
    if (warp == 0) {
        float vN = lane < 8 ? wN[lane] : 0.f;
        float vD = lane < 8 ? wD[lane] : 0.f;
        float vB = lane < 8 ? wB[lane] : 0.f;
#pragma unroll
        for (int off = 4; off > 0; off >>= 1) {
            vN += __shfl_down_sync(0xffffffffu, vN, off);
            vD += __shfl_down_sync(0xffffffffu, vD, off);
            vB += __shfl_down_sync(0xffffffffu, vB, off);
        }
        if (lane == 0) {
            g_part[3 * blockIdx.x + 0] = vN;
            g_part[3 * blockIdx.x + 1] = vD;
            g_part[3 * blockIdx.x + 2] = vB;
        }
    }

    __threadfence();
    if (tid == 0) {
        unsigned prev = atomicAdd(&g_count, 1u);
        is_last = (prev == B_BLOCKS - 1);
    }
    __syncthreads();
    if (!is_last) return;

    double sN = 0.0, sD = 0.0, sB = 0.0;
    for (int b = tid; b < B_BLOCKS; b += K2_BLK) {
        sN += (double)g_part[3 * b + 0];
        sD += (double)g_part[3 * b + 1];
        sB += (double)g_part[3 * b + 2];
    }
    __shared__ double rd[K2_BLK];
    rd[tid] = sN; __syncthreads();
    for (int s = K2_BLK / 2; s > 0; s >>= 1) { if (tid < s) rd[tid] += rd[tid + s]; __syncthreads(); }
    double tN = rd[0]; __syncthreads();
    rd[tid] = sD; __syncthreads();
    for (int s = K2_BLK / 2; s > 0; s >>= 1) { if (tid < s) rd[tid] += rd[tid + s]; __syncthreads(); }
    double tD = rd[0]; __syncthreads();
    rd[tid] = sB; __syncthreads();
    for (int s = K2_BLK / 2; s > 0; s >>= 1) { if (tid < s) rd[tid] += rd[tid + s]; __syncthreads(); }
    double tB = rd[0];

    if (tid == 0) {
        double dice = 1.0 - (2.0 * tN + 1e-3) / (tD + 1e-3);
        double vol = tB / (8.0 * NP_WIN);
        out[0] = (float)(dice + vol);
    }
}

// ---------------------------------------------------------------------------
extern "C" void kernel_launch(void* const* d_in, const int* in_sizes, int n_in,
                              void* d_out, int out_size) {
    const float* pred   = (const float*)d_in[0];
    const int*   labels = (const int*)d_in[1];
    const float* area   = (const float*)d_in[2];

    k1<<<NW, NPX>>>(pred, labels);
    k2<<<B_BLOCKS, K2_BLK>>>(area, (float*)d_out);
}

// round 14
// speedup vs baseline: 1.6261x; 1.6261x over previous
#include <cuda_runtime.h>
#include <cstdint>

// Problem dims (fixed)
#define ZD 16
#define YD 384
#define XD 384
#define YP 386        // padded y rows (row 0 and 385 stay zero)
#define NWIN_I 17     // z-pairs
#define NWIN_Y 385    // window rows
#define NGX 48        // 8-window groups; group 47 also does edge window x=384
#define TOTAL_B_THREADS (NWIN_I * NWIN_Y * NGX)          // 314160
#define K2_BLK 256
#define B_BLOCKS ((TOTAL_B_THREADS + K2_BLK - 1) / K2_BLK)   // 1228
#define NP_WIN 148225.0                                   // 385*385
#define SLAB (YD * XD)                                    // 147456

// Scratch (static __device__ — zero-initialized; padded rows never written)
__device__ float         g_E[NWIN_I * YP * XD];   // z-pair sums of (s-l)^2
__device__ unsigned char g_ZC[NWIN_I * YP * XD];  // z-pair code: l0@0,l1@2,p0@4,p1@6
__device__ float2        g_S[NWIN_I * YP * XD];   // z-pair sums of (softplus(p), softplus(-p))
__device__ float         g_part[3 * B_BLOCKS];
__device__ unsigned      g_count;

// ---------------------------------------------------------------------------
// k1: z-pass. One thread per (y,x) column; walks z, emits 17 z-pair
// (E, code, softplus-pair) records.  (identical to R12's proven k1)
__global__ void k1(const float* __restrict__ pred, const int* __restrict__ lab) {
    int x = threadIdx.x;
    int y = blockIdx.x;
    if (x == 0 && y == 0) g_count = 0u;
    int base = y * XD + x;
    int obase = (y + 1) * XD + x;   // padded row index

    float dprev = 0.f, spPrev = 0.f, snPrev = 0.f;
    unsigned cprev = 0u;
#pragma unroll 4
    for (int z = 0; z < ZD; z++) {
        float p = __ldg(&pred[z * SLAB + base]);
        int   l = __ldg(&lab[z * SLAB + base]);
        float s = __fdividef(1.f, 1.f + __expf(-p));
        float f = (float)l;
        float d = (s - f) * (s - f);
        float sp = fmaxf(p, 0.f) + __logf(1.f + __expf(-fabsf(p)));  // softplus(p)
        float sn = sp - p;                                           // softplus(-p)
        unsigned c = (unsigned)(l & 1) | (p > 0.f ? 0x10u : 0u);  // lab@0, pred@4
        int o = z * (YP * XD) + obase;
        g_E[o]  = dprev + d;
        g_ZC[o] = (unsigned char)(cprev | (c << 2));
        g_S[o]  = make_float2(spPrev + sp, snPrev + sn);
        dprev = d; spPrev = sp; snPrev = sn;
        cprev = c;
    }
    int o = ZD * (YP * XD) + obase;
    g_E[o]  = dprev;
    g_ZC[o] = (unsigned char)cprev;
    g_S[o]  = make_float2(spPrev, snPrev);
}

// ---------------------------------------------------------------------------
__device__ __forceinline__ float warp_sum(float v) {
#pragma unroll
    for (int off = 16; off > 0; off >>= 1)
        v += __shfl_down_sync(0xffffffffu, v, off);
    return v;
}

// ---------------------------------------------------------------------------
// k2: each thread sweeps 8 consecutive windows along x for a fixed (i, yw).
// Carry (Fp, cbp) comes from the previous lane via shuffle (it is that
// thread's last column); only lane0-with-g>0 threads load it explicitly.
__global__ void __launch_bounds__(K2_BLK, 8)
k2(const float* __restrict__ area, float* __restrict__ out) {
    __shared__ float a_sh[256];
    __shared__ float wN[8], wD[8], wB[8];
    __shared__ bool is_last;
    int tid = threadIdx.x;

    // permuted area LUT: index = (leftcol_nibble<<4)|rightcol_nibble,
    // nibble bit m = dz*2+dy -> true byte bit 2m+dx (left dx=0, right dx=1)
    {
        int a = tid >> 4, b = tid & 15;
        int byte = 0;
#pragma unroll
        for (int m = 0; m < 4; m++) {
            byte |= ((a >> m) & 1) << (2 * m);
            byte |= ((b >> m) & 1) << (2 * m + 1);
        }
        a_sh[tid] = __ldg(&area[byte]);
    }
    __syncthreads();

    float S1 = 0.f, S2 = 0.f, Sq = 0.f, accB = 0.f;
    int t = blockIdx.x * K2_BLK + tid;
    bool valid = (t < TOTAL_B_THREADS);

    int g = 0, yw = 0, i = 0, x0 = 0, rA = 0, rB = 0;
    float4 a0, a1, b0, b1;
    a0 = a1 = b0 = b1 = make_float4(0.f, 0.f, 0.f, 0.f);
    uint2 za = make_uint2(0u, 0u), zb = za;
    if (valid) {
        g = t % NGX;
        int rem = t / NGX;
        yw = rem % NWIN_Y;
        i = rem / NWIN_Y;
        x0 = g * 8;
        rA = (i * YP + yw) * XD;
        rB = rA + XD;

        const float4* pA = reinterpret_cast<const float4*>(g_E + rA + x0);
        const float4* pB = reinterpret_cast<const float4*>(g_E + rB + x0);
        a0 = pA[0]; a1 = pA[1];
        b0 = pB[0]; b1 = pB[1];
        za = *reinterpret_cast<const uint2*>(g_ZC + rA + x0);
        zb = *reinterpret_cast<const uint2*>(g_ZC + rB + x0);
    }

    // my last column (feeds next lane's carry)
    float myLastF = a1.w + b1.w;
    unsigned myLastC = (za.y | (zb.y << 1)) >> 24;
    float upF = __shfl_up_sync(0xffffffffu, myLastF, 1);
    unsigned upC = __shfl_up_sync(0xffffffffu, myLastC, 1);

    if (valid) {
        float Fp;
        unsigned cbp;
        int lane = tid & 31;
        if (g == 0) {
            Fp = 0.f;
            cbp = 0u;
        } else if (lane == 0) {
            int c = x0 - 1;
            Fp = g_E[rA + c] + g_E[rB + c];
            cbp = (unsigned)g_ZC[rA + c] | ((unsigned)g_ZC[rB + c] << 1);
        } else {
            Fp = upF;
            cbp = upC;
        }

#pragma unroll
        for (int j = 0; j < 2; j++) {
            float4 ea = j ? a1 : a0;
            float4 eb = j ? b1 : b0;
            // column codes for 4 columns: zc bytes <= 0x55 -> <<1 stays in-lane
            unsigned cw = (j ? za.y : za.x) | ((j ? zb.y : zb.x) << 1);
            // prevw byte k = code of column k-1 (byte0 = carry)
            unsigned prevw = __byte_perm(cw, cbp, 0x2104);
            // L byte k = lidx of window k ; P byte k = pidx of window k
            unsigned L = ((prevw << 4) & 0xF0F0F0F0u) | (cw & 0x0F0F0F0Fu);
            unsigned P = (prevw & 0xF0F0F0F0u) | ((cw >> 4) & 0x0F0F0F0Fu);

            float F0 = ea.x + eb.x;
            float F1 = ea.y + eb.y;
            float F2 = ea.z + eb.z;
            float F3 = ea.w + eb.w;

            float q0 = Fp + F0;
            float q1 = F0 + F1;
            float q2 = F1 + F2;
            float q3 = F2 + F3;

            float la0 = a_sh[L & 0xFFu];
            float la1 = a_sh[(L >> 8) & 0xFFu];
            float la2 = a_sh[(L >> 16) & 0xFFu];
            float la3 = a_sh[L >> 24];
            float pa0 = a_sh[P & 0xFFu];
            float pa1 = a_sh[(P >> 8) & 0xFFu];
            float pa2 = a_sh[(P >> 16) & 0xFFu];
            float pa3 = a_sh[P >> 24];

            Sq = fmaf(q0, la0, Sq);
            Sq = fmaf(q1, la1, Sq);
            Sq = fmaf(q2, la2, Sq);
            Sq = fmaf(q3, la3, Sq);
            S1 += (la0 + la1) + (la2 + la3);
            S2 += (pa0 + pa1) + (pa2 + pa3);

            // rare path: window label byte 0 -> sum softplus(p); 255 -> softplus(-p)
            unsigned r = __vcmpeq4(L, 0u) | __vcmpeq4(L, 0xFFFFFFFFu);
            if (r) {
#pragma unroll
                for (int k = 0; k < 4; k++) {
                    unsigned lb = (L >> (8 * k)) & 0xFFu;
                    if (lb == 0u || lb == 255u) {
                        int x = x0 + 4 * j + k;     // window; cols x-1, x
                        float2 sRA = g_S[rA + x];
                        float2 sRB = g_S[rB + x];
                        float s0 = sRA.x + sRB.x;
                        float s1 = sRA.y + sRB.y;
                        if (x > 0) {
                            float2 sLA = g_S[rA + x - 1];
                            float2 sLB = g_S[rB + x - 1];
                            s0 += sLA.x + sLB.x;
                            s1 += sLA.y + sLB.y;
                        }
                        accB += (lb == 255u) ? s1 : s0;
                    }
                }
            }

            Fp = F3;
            cbp = cw >> 24;
        }

        // group 47: edge window x=384 (right column is zero padding)
        if (g == NGX - 1) {
            float q = Fp;
            unsigned lidx = (cbp << 4) & 0xF0u;
            unsigned pidx = cbp & 0xF0u;
            float la = a_sh[lidx];
            float pa = a_sh[pidx];
            Sq = fmaf(q, la, Sq);
            S1 += la;
            S2 += pa;
            if (lidx == 0u) {   // lidx==255 impossible here (low nibble is 0)
                float2 sLA = g_S[rA + 383];
                float2 sLB = g_S[rB + 383];
                accB += sLA.x + sLB.x;
            }
        }
    }
    float accN = fmaf(Sq, -0.125f, S1);   // sum of (1 - q/8)*la
    float accD = S1 + S2;

    // deterministic warp-shuffle reduction
    accN = warp_sum(accN);
    accD = warp_sum(accD);
    accB = warp_sum(accB);
    int lane = tid & 31, warp = tid >> 5;
    if (lane == 0) { wN[warp] = accN; wD[warp] = accD; wB[warp] = accB; }
    __syncthreads();
    if (warp == 0) {
        float vN = lane < 8 ? wN[lane] : 0.f;
        float vD = lane < 8 ? wD[lane] : 0.f;
        float vB = lane < 8 ? wB[lane] : 0.f;
#pragma unroll
        for (int off = 4; off > 0; off >>= 1) {
            vN += __shfl_down_sync(0xffffffffu, vN, off);
            vD += __shfl_down_sync(0xffffffffu, vD, off);
            vB += __shfl_down_sync(0xffffffffu, vB, off);
        }
        if (lane == 0) {
            g_part[3 * blockIdx.x + 0] = vN;
            g_part[3 * blockIdx.x + 1] = vD;
            g_part[3 * blockIdx.x + 2] = vB;
        }
    }

    __threadfence();
    if (tid == 0) {
        unsigned prev = atomicAdd(&g_count, 1u);
        is_last = (prev == B_BLOCKS - 1);
    }
    __syncthreads();
    if (!is_last) return;

    double sN = 0.0, sD = 0.0, sB = 0.0;
    for (int b = tid; b < B_BLOCKS; b += K2_BLK) {
        sN += (double)g_part[3 * b + 0];
        sD += (double)g_part[3 * b + 1];
        sB += (double)g_part[3 * b + 2];
    }
    __shared__ double rd[K2_BLK];
    rd[tid] = sN; __syncthreads();
    for (int s = K2_BLK / 2; s > 0; s >>= 1) { if (tid < s) rd[tid] += rd[tid + s]; __syncthreads(); }
    double tN = rd[0]; __syncthreads();
    rd[tid] = sD; __syncthreads();
    for (int s = K2_BLK / 2; s > 0; s >>= 1) { if (tid < s) rd[tid] += rd[tid + s]; __syncthreads(); }
    double tD = rd[0]; __syncthreads();
    rd[tid] = sB; __syncthreads();
    for (int s = K2_BLK / 2; s > 0; s >>= 1) { if (tid < s) rd[tid] += rd[tid + s]; __syncthreads(); }
    double tB = rd[0];

    if (tid == 0) {
        double dice = 1.0 - (2.0 * tN + 1e-3) / (tD + 1e-3);
        double vol = tB / (8.0 * NP_WIN);
        out[0] = (float)(dice + vol);
    }
}

// ---------------------------------------------------------------------------
extern "C" void kernel_launch(void* const* d_in, const int* in_sizes, int n_in,
                              void* d_out, int out_size) {
    const float* pred   = (const float*)d_in[0];
    const int*   labels = (const int*)d_in[1];
    const float* area   = (const float*)d_in[2];

    k1<<<YD, XD>>>(pred, labels);
    k2<<<B_BLOCKS, K2_BLK>>>(area, (float*)d_out);
}